// round 1
// baseline (speedup 1.0000x reference)
#include <cuda_runtime.h>
#include <cstdint>

// SPIL layer, fused single kernel. Shapes fixed per reference:
//   B=8, N=4096, K=32, C=128, H=64, P=32 (POS_DIM), threshold 0.04
// Key algebraic optimization: output = (sum_k W_k * nf_k) @ z_w + (sum_k W_k) * z_b
// so the z transform runs on the K-aggregated features (32x fewer FLOPs) and
// neighbor_features is read from HBM exactly once.

#define BB 8
#define NN 4096
#define KK 32
#define CC 128
#define HH 64
#define PP 32
#define PTS 4               // points per CTA
#define ROWS 128            // PTS*KK neighbor rows per CTA
#define NF_STRIDE 132       // padded row stride (floats); 132%4==0 (16B align), 132%32==4 (bank spread)
#define THREADS 128
#define D_THR 0.04f

// smem float offsets
#define OFF_NF    0
#define OFF_THW   (OFF_NF + ROWS*NF_STRIDE)        // 16896
#define OFF_CF    (OFF_THW + CC*HH)                // +8192
#define OFF_FEAT  (OFF_CF + PTS*CC)                // +512
#define OFF_RF    (OFF_FEAT + PTS*HH)              // +256
#define OFF_RL    (OFF_RF + ROWS)                  // +128
#define OFF_W     (OFF_RL + ROWS)                  // +128
#define OFF_AGG   (OFF_W + ROWS)                   // +128
#define OFF_SW    (OFF_AGG + PTS*CC)               // +512
#define OFF_SI    (OFF_SW + PTS)                   // +4
#define OFF_CX    (OFF_SI + PTS)                   // +4
#define OFF_WTS   (OFF_CX + PTS*3)                 // +12
// s_wts sub-offsets (within OFF_WTS)
#define WM1   0
#define WM1B  96
#define WM2   128
#define WM2B  224
#define WPSI  256
#define WPSIB 320
#define WPHIB 328
#define WTHB  392
#define WZB   456
#define WTS_N 520
#define SMEM_FLOATS (OFF_WTS + WTS_N)
#define SMEM_BYTES (SMEM_FLOATS * 4)

typedef unsigned long long ull;

__device__ __forceinline__ ull pack2(float lo, float hi) {
    ull r;
    asm("mov.b64 %0, {%1,%2};" : "=l"(r) : "f"(lo), "f"(hi));
    return r;
}
__device__ __forceinline__ void unpack2(ull v, float& lo, float& hi) {
    asm("mov.b64 {%0,%1}, %2;" : "=f"(lo), "=f"(hi) : "l"(v));
}
__device__ __forceinline__ ull fma2(ull a, ull b, ull c) {
    ull d;
    asm("fma.rn.f32x2 %0, %1, %2, %3;" : "=l"(d) : "l"(a), "l"(b), "l"(c));
    return d;
}

__global__ void __launch_bounds__(THREADS)
spil_kernel(const float* __restrict__ center_xyz,
            const float* __restrict__ center_features,
            const float* __restrict__ neighbor_xyz,
            const float* __restrict__ neighbor_features,
            const float* __restrict__ phi_w,  const float* __restrict__ phi_b,
            const float* __restrict__ theta_w,const float* __restrict__ theta_b,
            const float* __restrict__ m1_w,   const float* __restrict__ m1_b,
            const float* __restrict__ m2_w,   const float* __restrict__ m2_b,
            const float* __restrict__ psi_w,  const float* __restrict__ psi_b,
            const float* __restrict__ z_w,    const float* __restrict__ z_b,
            float* __restrict__ out)
{
    extern __shared__ float sm[];
    float* s_nf   = sm + OFF_NF;
    float* s_thw  = sm + OFF_THW;
    float* s_cf   = sm + OFF_CF;
    float* s_feat = sm + OFF_FEAT;
    float* s_rf   = sm + OFF_RF;
    float* s_rl   = sm + OFF_RL;
    float* s_W    = sm + OFF_W;
    float* s_agg  = sm + OFF_AGG;
    float* s_sW   = sm + OFF_SW;
    float* s_si   = sm + OFF_SI;
    float* s_cx   = sm + OFF_CX;
    float* s_wts  = sm + OFF_WTS;

    const int tid = threadIdx.x;
    const int bn0 = blockIdx.x * PTS;

    // ---------------- Phase 1: loads into smem ----------------
    // neighbor_features tile: ROWS x CC, padded stride. Coalesced float4, conflict-free stores.
    {
        const float4* nfg = (const float4*)(neighbor_features + (size_t)bn0 * KK * CC);
        #pragma unroll
        for (int it = 0; it < 32; ++it) {
            int v4 = it * THREADS + tid;          // float4 index 0..4095
            float4 v = __ldg(&nfg[v4]);
            int flat = v4 * 4;
            int row = flat >> 7, c = flat & 127;
            *(float4*)&s_nf[row * NF_STRIDE + c] = v;
        }
        // theta_w -> smem (8192 floats)
        const float4* tg = (const float4*)theta_w;
        #pragma unroll
        for (int i = tid; i < 2048; i += THREADS) ((float4*)s_thw)[i] = __ldg(&tg[i]);
        // center features (4x128)
        const float4* cg = (const float4*)(center_features + (size_t)bn0 * CC);
        ((float4*)s_cf)[tid] = __ldg(&cg[tid]);
        // center xyz
        if (tid < PTS * 3) s_cx[tid] = center_xyz[(size_t)bn0 * 3 + tid];
        // small weights
        for (int i = tid; i < 96; i += THREADS) { s_wts[WM1 + i] = m1_w[i]; s_wts[WM2 + i] = m2_w[i]; }
        if (tid < 32) { s_wts[WM1B + tid] = m1_b[tid]; s_wts[WM2B + tid] = m2_b[tid]; }
        if (tid < 64) {
            s_wts[WPSI  + tid] = psi_w[tid];
            s_wts[WPHIB + tid] = phi_b[tid];
            s_wts[WTHB  + tid] = theta_b[tid];
            s_wts[WZB   + tid] = z_b[tid];
        }
        if (tid == 0) s_wts[WPSIB] = psi_b[0];
    }
    __syncthreads();

    // ---------------- Phase 2: pos scores / mask (per row) + feat_i (phi GEMV) ----------------
    const int p_r = tid >> 5;            // row tid -> point
    float score_j, rl_mask_kill;
    {
        const float* nx = neighbor_xyz + ((size_t)bn0 * KK + tid) * 3;
        float nx0 = nx[0], nx1 = nx[1], nx2 = nx[2];
        float cx0 = s_cx[p_r * 3], cx1 = s_cx[p_r * 3 + 1], cx2 = s_cx[p_r * 3 + 2];
        float sj = 0.f;
        #pragma unroll
        for (int d = 0; d < PP; ++d) {
            float pj = fmaf(nx0, s_wts[WM2 + d],
                       fmaf(nx1, s_wts[WM2 + 32 + d],
                       fmaf(nx2, s_wts[WM2 + 64 + d], s_wts[WM2B + d])));
            sj = fmaf(fmaxf(pj, 0.f), s_wts[WPSI + 32 + d], sj);
        }
        score_j = sj;
        float dx = cx0 - nx0, dy = cx1 - nx1, dz = cx2 - nx2;
        float dist = sqrtf(dx * dx + dy * dy + dz * dz);
        bool masked = (cx2 == nx2) && (dist > D_THR);
        rl_mask_kill = masked ? 0.f : 1.f;
    }
    // score_i per point (redundant-free: 4 threads)
    if (tid < PTS) {
        float cx0 = s_cx[tid * 3], cx1 = s_cx[tid * 3 + 1], cx2 = s_cx[tid * 3 + 2];
        float si = 0.f;
        #pragma unroll
        for (int d = 0; d < PP; ++d) {
            float pi = fmaf(cx0, s_wts[WM1 + d],
                       fmaf(cx1, s_wts[WM1 + 32 + d],
                       fmaf(cx2, s_wts[WM1 + 64 + d], s_wts[WM1B + d])));
            si = fmaf(fmaxf(pi, 0.f), s_wts[WPSI + d], si);
        }
        s_si[tid] = si;
    }
    // feat_i = relu(cf @ phi_w + b): thread (h, pg) does 2 points sharing the phi column
    {
        const int h = tid & 63, pg = tid >> 6;
        float a0 = s_wts[WPHIB + h], a1 = a0;
        const float* pw = phi_w + h;
        const float* cfa = s_cf + (2 * pg) * CC;
        const float* cfb = s_cf + (2 * pg + 1) * CC;
        #pragma unroll 8
        for (int c = 0; c < CC; ++c) {
            float w = __ldg(pw + c * HH);
            a0 = fmaf(cfa[c], w, a0);
            a1 = fmaf(cfb[c], w, a1);
        }
        s_feat[(2 * pg) * HH + h]     = fmaxf(a0, 0.f);
        s_feat[(2 * pg + 1) * HH + h] = fmaxf(a1, 0.f);
    }
    __syncthreads();
    // r_l for my row (uses s_si, written before the sync above)
    s_rl[tid] = fmaxf(s_si[p_r] + score_j + s_wts[WPSIB], 0.f) * rl_mask_kill;

    // ---------------- Phase 3: theta GEMM (128 rows x 64 cols x 128) with f32x2 ----------------
    // thread tile: 8 rows (stride 16) x 8 cols; lane layout cg=tid&7, rg=tid>>3 keeps
    // nf loads conflict-free (4 distinct rows/warp, bank spread of 4 via stride 132).
    const int cg = tid & 7, rg = tid >> 3;
    const int h0 = cg * 8;
    ull acc[8][4];
    {
        ull b0 = pack2(s_wts[WTHB + h0 + 0], s_wts[WTHB + h0 + 1]);
        ull b1 = pack2(s_wts[WTHB + h0 + 2], s_wts[WTHB + h0 + 3]);
        ull b2 = pack2(s_wts[WTHB + h0 + 4], s_wts[WTHB + h0 + 5]);
        ull b3 = pack2(s_wts[WTHB + h0 + 6], s_wts[WTHB + h0 + 7]);
        #pragma unroll
        for (int i = 0; i < 8; ++i) { acc[i][0] = b0; acc[i][1] = b1; acc[i][2] = b2; acc[i][3] = b3; }
    }
    #pragma unroll 2
    for (int c = 0; c < CC; ++c) {
        ulonglong2 t0 = *(const ulonglong2*)&s_thw[c * HH + h0];
        ulonglong2 t1 = *(const ulonglong2*)&s_thw[c * HH + h0 + 4];
        #pragma unroll
        for (int i = 0; i < 8; ++i) {
            float v = s_nf[(rg + 16 * i) * NF_STRIDE + c];
            ull vv = pack2(v, v);
            acc[i][0] = fma2(vv, t0.x, acc[i][0]);
            acc[i][1] = fma2(vv, t0.y, acc[i][1]);
            acc[i][2] = fma2(vv, t1.x, acc[i][2]);
            acc[i][3] = fma2(vv, t1.y, acc[i][3]);
        }
    }
    // epilogue: r_f[row] = sum_h feat_i[p][h] * relu(theta[row][h]); reduce over 8 col-groups
    {
        float rpart[8];
        #pragma unroll
        for (int i = 0; i < 8; ++i) {
            int row = rg + 16 * i;
            const float* fp = s_feat + (row >> 5) * HH + h0;
            float r = 0.f;
            #pragma unroll
            for (int pr = 0; pr < 4; ++pr) {
                float lo, hi;
                unpack2(acc[i][pr], lo, hi);
                r = fmaf(fmaxf(lo, 0.f), fp[2 * pr], r);
                r = fmaf(fmaxf(hi, 0.f), fp[2 * pr + 1], r);
            }
            rpart[i] = r;
        }
        #pragma unroll
        for (int ofs = 1; ofs < 8; ofs <<= 1) {
            #pragma unroll
            for (int i = 0; i < 8; ++i)
                rpart[i] += __shfl_xor_sync(0xffffffffu, rpart[i], ofs);
        }
        if (cg == 0) {
            #pragma unroll
            for (int i = 0; i < 8; ++i) s_rf[rg + 16 * i] = rpart[i];
        }
    }
    __syncthreads();

    // ---------------- Phase 4: masked r_l-weighted softmax + K-aggregation (warp per point) ----
    {
        const int wp = tid >> 5;      // point
        const int lk = tid & 31;      // k
        const int row = wp * 32 + lk;
        float rf = s_rf[row] * 0.125f;       // / sqrt(64)
        float m = rf;
        #pragma unroll
        for (int ofs = 16; ofs > 0; ofs >>= 1) m = fmaxf(m, __shfl_xor_sync(0xffffffffu, m, ofs));
        float e = s_rl[row] * expf(rf - m);
        float sum = e;
        #pragma unroll
        for (int ofs = 16; ofs > 0; ofs >>= 1) sum += __shfl_xor_sync(0xffffffffu, sum, ofs);
        float denom = sum + 1e-8f;
        s_W[row] = e / denom;
        if (lk == 0) s_sW[wp] = sum / denom;
        __syncwarp();
        // agg[p][c] = sum_k W[k] * nf[p*32+k][c]; lane handles 4 c values
        float a0 = 0.f, a1 = 0.f, a2 = 0.f, a3 = 0.f;
        #pragma unroll
        for (int k = 0; k < KK; ++k) {
            float w = s_W[wp * 32 + k];
            const float* nr = &s_nf[(wp * 32 + k) * NF_STRIDE + lk];
            a0 = fmaf(w, nr[0],  a0);
            a1 = fmaf(w, nr[32], a1);
            a2 = fmaf(w, nr[64], a2);
            a3 = fmaf(w, nr[96], a3);
        }
        s_agg[wp * CC + lk]      = a0;
        s_agg[wp * CC + lk + 32] = a1;
        s_agg[wp * CC + lk + 64] = a2;
        s_agg[wp * CC + lk + 96] = a3;
    }
    __syncthreads();

    // ---------------- Phase 5: z GEMV on aggregated features + write out ----------------
    {
        const int h = tid & 63, pg = tid >> 6;
        const int pA = 2 * pg, pB = 2 * pg + 1;
        float aA = s_sW[pA] * s_wts[WZB + h];
        float aB = s_sW[pB] * s_wts[WZB + h];
        const float* zw = z_w + h;
        const float* gA = s_agg + pA * CC;
        const float* gB = s_agg + pB * CC;
        #pragma unroll 8
        for (int c = 0; c < CC; ++c) {
            float w = __ldg(zw + c * HH);
            aA = fmaf(gA[c], w, aA);
            aB = fmaf(gB[c], w, aB);
        }
        out[(size_t)(bn0 + pA) * HH + h] = aA;
        out[(size_t)(bn0 + pB) * HH + h] = aB;
    }
}

extern "C" void kernel_launch(void* const* d_in, const int* in_sizes, int n_in,
                              void* d_out, int out_size)
{
    (void)in_sizes; (void)n_in; (void)out_size;
    const float* center_xyz        = (const float*)d_in[0];
    const float* center_features   = (const float*)d_in[1];
    const float* neighbor_xyz      = (const float*)d_in[2];
    const float* neighbor_features = (const float*)d_in[3];
    const float* phi_w   = (const float*)d_in[4];
    const float* phi_b   = (const float*)d_in[5];
    const float* theta_w = (const float*)d_in[6];
    const float* theta_b = (const float*)d_in[7];
    const float* m1_w    = (const float*)d_in[8];
    const float* m1_b    = (const float*)d_in[9];
    const float* m2_w    = (const float*)d_in[10];
    const float* m2_b    = (const float*)d_in[11];
    const float* psi_w   = (const float*)d_in[12];
    const float* psi_b   = (const float*)d_in[13];
    const float* z_w     = (const float*)d_in[14];
    const float* z_b     = (const float*)d_in[15];
    float* out = (float*)d_out;

    cudaFuncSetAttribute(spil_kernel, cudaFuncAttributeMaxDynamicSharedMemorySize, SMEM_BYTES);
    dim3 grid(BB * NN / PTS);   // 8192
    dim3 block(THREADS);
    spil_kernel<<<grid, block, SMEM_BYTES>>>(
        center_xyz, center_features, neighbor_xyz, neighbor_features,
        phi_w, phi_b, theta_w, theta_b, m1_w, m1_b, m2_w, m2_b,
        psi_w, psi_b, z_w, z_b, out);
}

// round 3
// speedup vs baseline: 1.5810x; 1.5810x over previous
#include <cuda_runtime.h>
#include <cuda_bf16.h>
#include <cstdint>

// SPIL layer, fused single kernel, theta-GEMM on tensor cores via mma.sync
// (bf16 hi/lo x3 split; tcgen05 is unavailable: harness PTX targets compute_103).
// Shapes fixed: B=8, N=4096, K=32, C=128, H=64, P=32, threshold 0.04
// Algebra: out = (sum_k W_k nf_k) @ z_w + (sum_k W_k) z_b  (z GEMM shrunk 32x)
// Per CTA: 4 points -> 128 neighbor rows. D[128,64] = nf[128,128] @ theta_w^T.
// Warp w owns rows 32w..32w+31 == point w (same mapping through softmax/agg).

#define BB 8
#define NN 4096
#define KK 32
#define CC 128
#define HH 64
#define PP 32
#define PTS 4
#define ROWS 128
#define THREADS 128
#define D_THR 0.04f

// ---- smem byte layout ----
// A (nf) hi/lo: 128 rows x 136 bf16 (272B rows, 16B aligned, ldmatrix-friendly)
// B (theta^T as [c][h]) hi/lo: 128 rows x 72 bf16 (144B rows)
#define A_STR 136
#define B_STR 72
#define SM_A_HI 0
#define SM_A_LO (SM_A_HI + ROWS * A_STR * 2)        // 34816
#define SM_B_HI (SM_A_LO + ROWS * A_STR * 2)        // 69632
#define SM_B_LO (SM_B_HI + CC * B_STR * 2)          // 88064
#define SM_FLT  (SM_B_LO + CC * B_STR * 2)          // 106496
// float offsets within scalar region
#define F_CF    0          // 512 floats (aliased with s_agg after phase 2)
#define F_FEAT  512        // 256
#define F_RF    768        // 128
#define F_SW    896        // 4
#define F_SI    900        // 4
#define F_CX    904        // 12
#define F_WTS   916        // 520
#define WM1   0
#define WM1B  96
#define WM2   128
#define WM2B  224
#define WPSI  256
#define WPSIB 320
#define WPHIB 328
#define WTHB  392
#define WZB   456
#define FLT_N  1436
#define SMEM_TOTAL (SM_FLT + FLT_N * 4)             // 112240 bytes -> 2 CTAs/SM

__device__ __forceinline__ uint32_t smem_to_u32(const void* p) {
    uint32_t a;
    asm("{ .reg .u64 t; cvta.to.shared.u64 t, %1; cvt.u32.u64 %0, t; }" : "=r"(a) : "l"(p));
    return a;
}
__device__ __forceinline__ void ldsm_x4(uint32_t* r, uint32_t addr) {
    asm volatile("ldmatrix.sync.aligned.m8n8.x4.shared.b16 {%0,%1,%2,%3}, [%4];"
                 : "=r"(r[0]), "=r"(r[1]), "=r"(r[2]), "=r"(r[3]) : "r"(addr));
}
__device__ __forceinline__ void ldsm_x4_t(uint32_t* r, uint32_t addr) {
    asm volatile("ldmatrix.sync.aligned.m8n8.x4.trans.shared.b16 {%0,%1,%2,%3}, [%4];"
                 : "=r"(r[0]), "=r"(r[1]), "=r"(r[2]), "=r"(r[3]) : "r"(addr));
}
__device__ __forceinline__ void mma16816(float* d, const uint32_t* a, const uint32_t* b) {
    asm volatile("mma.sync.aligned.m16n8k16.row.col.f32.bf16.bf16.f32 "
                 "{%0,%1,%2,%3}, {%4,%5,%6,%7}, {%8,%9}, {%0,%1,%2,%3};"
                 : "+f"(d[0]), "+f"(d[1]), "+f"(d[2]), "+f"(d[3])
                 : "r"(a[0]), "r"(a[1]), "r"(a[2]), "r"(a[3]), "r"(b[0]), "r"(b[1]));
}

__global__ void __launch_bounds__(THREADS)
spil_kernel(const float* __restrict__ center_xyz,
            const float* __restrict__ center_features,
            const float* __restrict__ neighbor_xyz,
            const float* __restrict__ neighbor_features,
            const float* __restrict__ phi_w,  const float* __restrict__ phi_b,
            const float* __restrict__ theta_w,const float* __restrict__ theta_b,
            const float* __restrict__ m1_w,   const float* __restrict__ m1_b,
            const float* __restrict__ m2_w,   const float* __restrict__ m2_b,
            const float* __restrict__ psi_w,  const float* __restrict__ psi_b,
            const float* __restrict__ z_w,    const float* __restrict__ z_b,
            float* __restrict__ out)
{
    extern __shared__ char smem[];
    const uint32_t sbase = smem_to_u32(smem);
    char* sA_hi = smem + SM_A_HI;
    char* sA_lo = smem + SM_A_LO;
    char* sB_hi = smem + SM_B_HI;
    char* sB_lo = smem + SM_B_LO;
    float* s_f    = (float*)(smem + SM_FLT);
    float* s_cf   = s_f + F_CF;
    float* s_agg  = s_f + F_CF;     // alias: cf dead after phase 2
    float* s_feat = s_f + F_FEAT;
    float* s_rf   = s_f + F_RF;
    float* s_sW   = s_f + F_SW;
    float* s_si   = s_f + F_SI;
    float* s_cx   = s_f + F_CX;
    float* s_wts  = s_f + F_WTS;

    const int tid = threadIdx.x;
    const int wid = tid >> 5;
    const int lid = tid & 31;
    const int bn0 = blockIdx.x * PTS;

    // ---------------- Phase 1: load + bf16 hi/lo split into smem ----------------
    {
        // nf tile: 16K floats, coalesced float4. row = flat>>7, c = flat&127.
        const float4* nfg = (const float4*)(neighbor_features + (size_t)bn0 * KK * CC);
        #pragma unroll
        for (int it = 0; it < 32; ++it) {
            int v4 = it * THREADS + tid;
            float4 v = __ldg(&nfg[v4]);
            int flat = v4 * 4;
            int row = flat >> 7, c = flat & 127;
            __nv_bfloat162 h01 = __float22bfloat162_rn(make_float2(v.x, v.y));
            __nv_bfloat162 h23 = __float22bfloat162_rn(make_float2(v.z, v.w));
            float2 f01 = __bfloat1622float2(h01);
            float2 f23 = __bfloat1622float2(h23);
            __nv_bfloat162 l01 = __float22bfloat162_rn(make_float2(v.x - f01.x, v.y - f01.y));
            __nv_bfloat162 l23 = __float22bfloat162_rn(make_float2(v.z - f23.x, v.w - f23.y));
            uint32_t o = (uint32_t)(row * A_STR + c) * 2;
            *(__nv_bfloat162*)(sA_hi + o)     = h01;
            *(__nv_bfloat162*)(sA_hi + o + 4) = h23;
            *(__nv_bfloat162*)(sA_lo + o)     = l01;
            *(__nv_bfloat162*)(sA_lo + o + 4) = l23;
        }
        // theta_w [c][h] row-major -> B smem [c][h] (natural layout, 8B stores)
        const float4* tg = (const float4*)theta_w;
        #pragma unroll
        for (int i = tid; i < 2048; i += THREADS) {
            float4 v = __ldg(&tg[i]);
            int c = i >> 4, h = (i & 15) * 4;
            __nv_bfloat162 h01 = __float22bfloat162_rn(make_float2(v.x, v.y));
            __nv_bfloat162 h23 = __float22bfloat162_rn(make_float2(v.z, v.w));
            float2 f01 = __bfloat1622float2(h01);
            float2 f23 = __bfloat1622float2(h23);
            __nv_bfloat162 l01 = __float22bfloat162_rn(make_float2(v.x - f01.x, v.y - f01.y));
            __nv_bfloat162 l23 = __float22bfloat162_rn(make_float2(v.z - f23.x, v.w - f23.y));
            uint32_t o = (uint32_t)(c * B_STR + h) * 2;
            *(__nv_bfloat162*)(sB_hi + o)     = h01;
            *(__nv_bfloat162*)(sB_hi + o + 4) = h23;
            *(__nv_bfloat162*)(sB_lo + o)     = l01;
            *(__nv_bfloat162*)(sB_lo + o + 4) = l23;
        }
        // center features (4x128)
        const float4* cg = (const float4*)(center_features + (size_t)bn0 * CC);
        ((float4*)s_cf)[tid] = __ldg(&cg[tid]);
        if (tid < PTS * 3) s_cx[tid] = center_xyz[(size_t)bn0 * 3 + tid];
        for (int i = tid; i < 96; i += THREADS) { s_wts[WM1 + i] = m1_w[i]; s_wts[WM2 + i] = m2_w[i]; }
        if (tid < 32) { s_wts[WM1B + tid] = m1_b[tid]; s_wts[WM2B + tid] = m2_b[tid]; }
        if (tid < 64) {
            s_wts[WPSI  + tid] = psi_w[tid];
            s_wts[WPHIB + tid] = phi_b[tid];
            s_wts[WTHB  + tid] = theta_b[tid];
            s_wts[WZB   + tid] = z_b[tid];
        }
        if (tid == 0) s_wts[WPSIB] = psi_b[0];
    }
    __syncthreads();

    // ---------------- Phase 2: pos score + mask (row = tid), feat_i phi-GEMV ----
    const int p_r = tid >> 5;
    float score_j, kill;
    {
        const float* nx = neighbor_xyz + ((size_t)bn0 * KK + tid) * 3;
        float nx0 = nx[0], nx1 = nx[1], nx2 = nx[2];
        float cx0 = s_cx[p_r * 3], cx1 = s_cx[p_r * 3 + 1], cx2 = s_cx[p_r * 3 + 2];
        float sj = 0.f;
        #pragma unroll
        for (int d = 0; d < PP; ++d) {
            float pj = fmaf(nx0, s_wts[WM2 + d],
                       fmaf(nx1, s_wts[WM2 + 32 + d],
                       fmaf(nx2, s_wts[WM2 + 64 + d], s_wts[WM2B + d])));
            sj = fmaf(fmaxf(pj, 0.f), s_wts[WPSI + 32 + d], sj);
        }
        score_j = sj;
        float dx = cx0 - nx0, dy = cx1 - nx1, dz = cx2 - nx2;
        float dist = sqrtf(dx * dx + dy * dy + dz * dz);
        bool masked = (cx2 == nx2) && (dist > D_THR);
        kill = masked ? 0.f : 1.f;
    }
    if (tid < PTS) {
        float cx0 = s_cx[tid * 3], cx1 = s_cx[tid * 3 + 1], cx2 = s_cx[tid * 3 + 2];
        float si = 0.f;
        #pragma unroll
        for (int d = 0; d < PP; ++d) {
            float pi = fmaf(cx0, s_wts[WM1 + d],
                       fmaf(cx1, s_wts[WM1 + 32 + d],
                       fmaf(cx2, s_wts[WM1 + 64 + d], s_wts[WM1B + d])));
            si = fmaf(fmaxf(pi, 0.f), s_wts[WPSI + d], si);
        }
        s_si[tid] = si;
    }
    {
        const int h = tid & 63, pg = tid >> 6;
        float a0 = s_wts[WPHIB + h], a1 = a0;
        const float* pw = phi_w + h;
        const float* cfa = s_cf + (2 * pg) * CC;
        const float* cfb = s_cf + (2 * pg + 1) * CC;
        #pragma unroll 8
        for (int c = 0; c < CC; ++c) {
            float w = __ldg(pw + c * HH);
            a0 = fmaf(cfa[c], w, a0);
            a1 = fmaf(cfb[c], w, a1);
        }
        s_feat[(2 * pg) * HH + h]     = fmaxf(a0, 0.f);
        s_feat[(2 * pg + 1) * HH + h] = fmaxf(a1, 0.f);
    }
    __syncthreads();
    const float r_l = fmaxf(s_si[p_r] + score_j + s_wts[WPSIB], 0.f) * kill;

    // ---------------- Phase 3: warp-local HMMA GEMM, D[32x64] per warp ----------
    // acc[mt][nt][4]: m16n8 fragments; 3 passes: Ahi*Bhi + Ahi*Blo + Alo*Bhi.
    float acc[2][8][4];
    #pragma unroll
    for (int mt = 0; mt < 2; ++mt)
        #pragma unroll
        for (int nt = 0; nt < 8; ++nt)
            #pragma unroll
            for (int e = 0; e < 4; ++e) acc[mt][nt][e] = 0.f;

    // ldmatrix lane addresses (byte offsets into smem)
    // A (x4, non-trans): lanes 0-7 rows 0-7 @k0 | 8-15 rows 8-15 @k0 | 16-23 rows 0-7 @k8 | 24-31 rows 8-15 @k8
    const uint32_t a_row = (uint32_t)(wid * 32 + (lid & 15));
    const uint32_t a_col0 = (uint32_t)((lid >> 4) * 8);
    const uint32_t aoff = (a_row * A_STR + a_col0) * 2;
    // B (x4, trans) over [c][h]: lanes 0-15 rows c0..c0+15 @h0 | 16-31 rows c0..c0+15 @h0+8
    const uint32_t b_rowl = (uint32_t)(lid & 15);
    const uint32_t b_colq = (uint32_t)((lid >> 4) * 8);

    #pragma unroll
    for (int kc = 0; kc < 8; ++kc) {
        uint32_t aA = sbase + SM_A_HI + aoff + (uint32_t)(kc * 32);            // +16 cols
        uint32_t aL = sbase + SM_A_LO + aoff + (uint32_t)(kc * 32);
        uint32_t ah[2][4], al[2][4];
        ldsm_x4(ah[0], aA);
        ldsm_x4(ah[1], aA + 16 * A_STR * 2);
        ldsm_x4(al[0], aL);
        ldsm_x4(al[1], aL + 16 * A_STR * 2);

        uint32_t brow = (uint32_t)(kc * 16) + b_rowl;
        uint32_t bh[8][2], bl[8][2];
        #pragma unroll
        for (int p = 0; p < 4; ++p) {
            uint32_t bo = (brow * B_STR + 16 * p + b_colq) * 2;
            uint32_t r[4];
            ldsm_x4_t(r, sbase + SM_B_HI + bo);
            bh[2*p][0] = r[0]; bh[2*p][1] = r[1]; bh[2*p+1][0] = r[2]; bh[2*p+1][1] = r[3];
            ldsm_x4_t(r, sbase + SM_B_LO + bo);
            bl[2*p][0] = r[0]; bl[2*p][1] = r[1]; bl[2*p+1][0] = r[2]; bl[2*p+1][1] = r[3];
        }
        #pragma unroll
        for (int mt = 0; mt < 2; ++mt)
            #pragma unroll
            for (int nt = 0; nt < 8; ++nt) {
                mma16816(acc[mt][nt], ah[mt], bh[nt]);
                mma16816(acc[mt][nt], ah[mt], bl[nt]);
                mma16816(acc[mt][nt], al[mt], bh[nt]);
            }
    }

    // ---------------- Phase 4: r_f reduction in fragment layout + softmax ------
    {
        const int g = lid >> 2, t = lid & 3;
        const float* fp = s_feat + wid * HH;
        float r4[4];
        #pragma unroll
        for (int mt = 0; mt < 2; ++mt) {
            float rA = 0.f, rB = 0.f;
            #pragma unroll
            for (int nt = 0; nt < 8; ++nt) {
                int h0 = nt * 8 + t * 2, h1 = h0 + 1;
                float tb0 = s_wts[WTHB + h0], tb1 = s_wts[WTHB + h1];
                float f0 = fp[h0], f1 = fp[h1];
                rA = fmaf(fmaxf(acc[mt][nt][0] + tb0, 0.f), f0, rA);
                rA = fmaf(fmaxf(acc[mt][nt][1] + tb1, 0.f), f1, rA);
                rB = fmaf(fmaxf(acc[mt][nt][2] + tb0, 0.f), f0, rB);
                rB = fmaf(fmaxf(acc[mt][nt][3] + tb1, 0.f), f1, rB);
            }
            r4[mt * 2]     = rA;   // row g + 16*mt
            r4[mt * 2 + 1] = rB;   // row g + 8 + 16*mt
        }
        #pragma unroll
        for (int i = 0; i < 4; ++i) {
            r4[i] += __shfl_xor_sync(0xffffffffu, r4[i], 1);
            r4[i] += __shfl_xor_sync(0xffffffffu, r4[i], 2);
        }
        if (t == 0) {
            s_rf[wid * 32 + g]      = r4[0];
            s_rf[wid * 32 + g + 8]  = r4[1];
            s_rf[wid * 32 + g + 16] = r4[2];
            s_rf[wid * 32 + g + 24] = r4[3];
        }
    }
    __syncwarp();

    float Wk;
    {
        float rf = s_rf[wid * 32 + lid] * 0.125f;     // / sqrt(64)
        float m = rf;
        #pragma unroll
        for (int ofs = 16; ofs > 0; ofs >>= 1) m = fmaxf(m, __shfl_xor_sync(0xffffffffu, m, ofs));
        float e = r_l * __expf(rf - m);
        float s = e;
        #pragma unroll
        for (int ofs = 16; ofs > 0; ofs >>= 1) s += __shfl_xor_sync(0xffffffffu, s, ofs);
        float denom = s + 1e-8f;
        Wk = e / denom;
        if (lid == 0) s_sW[wid] = s / denom;
    }

    // aggregation: agg[p][c] = sum_k W_k nf[p*32+k][c]; nf = hi + lo from smem.
    // lane handles c pairs {2l, 2l+1} and {64+2l, 65+2l} (bf162 loads, 1 wf each)
    {
        float2 a01 = make_float2(0.f, 0.f), a23 = make_float2(0.f, 0.f);
        #pragma unroll
        for (int k = 0; k < KK; ++k) {
            float wk = __shfl_sync(0xffffffffu, Wk, k);
            uint32_t ro = (uint32_t)((wid * KK + k) * A_STR) * 2;
            uint32_t o0 = ro + (uint32_t)(4 * lid);
            uint32_t o1 = o0 + 128;
            float2 h0 = __bfloat1622float2(*(__nv_bfloat162*)(sA_hi + o0));
            float2 l0 = __bfloat1622float2(*(__nv_bfloat162*)(sA_lo + o0));
            float2 h1 = __bfloat1622float2(*(__nv_bfloat162*)(sA_hi + o1));
            float2 l1 = __bfloat1622float2(*(__nv_bfloat162*)(sA_lo + o1));
            a01.x = fmaf(wk, h0.x + l0.x, a01.x);
            a01.y = fmaf(wk, h0.y + l0.y, a01.y);
            a23.x = fmaf(wk, h1.x + l1.x, a23.x);
            a23.y = fmaf(wk, h1.y + l1.y, a23.y);
        }
        s_agg[wid * CC + 2 * lid]      = a01.x;
        s_agg[wid * CC + 2 * lid + 1]  = a01.y;
        s_agg[wid * CC + 64 + 2 * lid] = a23.x;
        s_agg[wid * CC + 65 + 2 * lid] = a23.y;
    }
    __syncthreads();

    // ---------------- Phase 5: z GEMV on aggregated features + store ------------
    {
        const int h = tid & 63, pg = tid >> 6;
        const int pA = 2 * pg, pB = 2 * pg + 1;
        float aA = s_sW[pA] * s_wts[WZB + h];
        float aB = s_sW[pB] * s_wts[WZB + h];
        const float* zw = z_w + h;
        const float* gA = s_agg + pA * CC;
        const float* gB = s_agg + pB * CC;
        #pragma unroll 8
        for (int c = 0; c < CC; ++c) {
            float w = __ldg(zw + c * HH);
            aA = fmaf(gA[c], w, aA);
            aB = fmaf(gB[c], w, aB);
        }
        out[(size_t)(bn0 + pA) * HH + h] = aA;
        out[(size_t)(bn0 + pB) * HH + h] = aB;
    }
}

extern "C" void kernel_launch(void* const* d_in, const int* in_sizes, int n_in,
                              void* d_out, int out_size)
{
    (void)in_sizes; (void)n_in; (void)out_size;
    const float* center_xyz        = (const float*)d_in[0];
    const float* center_features   = (const float*)d_in[1];
    const float* neighbor_xyz      = (const float*)d_in[2];
    const float* neighbor_features = (const float*)d_in[3];
    const float* phi_w   = (const float*)d_in[4];
    const float* phi_b   = (const float*)d_in[5];
    const float* theta_w = (const float*)d_in[6];
    const float* theta_b = (const float*)d_in[7];
    const float* m1_w    = (const float*)d_in[8];
    const float* m1_b    = (const float*)d_in[9];
    const float* m2_w    = (const float*)d_in[10];
    const float* m2_b    = (const float*)d_in[11];
    const float* psi_w   = (const float*)d_in[12];
    const float* psi_b   = (const float*)d_in[13];
    const float* z_w     = (const float*)d_in[14];
    const float* z_b     = (const float*)d_in[15];
    float* out = (float*)d_out;

    cudaFuncSetAttribute(spil_kernel, cudaFuncAttributeMaxDynamicSharedMemorySize, SMEM_TOTAL);
    dim3 grid(BB * NN / PTS);   // 8192
    dim3 block(THREADS);
    spil_kernel<<<grid, block, SMEM_TOTAL>>>(
        center_xyz, center_features, neighbor_xyz, neighbor_features,
        phi_w, phi_b, theta_w, theta_b, m1_w, m1_b, m2_w, m2_b,
        psi_w, psi_b, z_w, z_b, out);
}